// round 14
// baseline (speedup 1.0000x reference)
#include <cuda_runtime.h>
#include <math.h>

// ---------------------------------------------------------------------------
// GRU T=512 B=64 IC=HC=512 L=2 — fused wavefront persistent kernel, v2.
//
// 128 CTAs x 512 threads: c<64 -> layer 1, c>=64 -> layer 2 (1-step skew).
// Each CTA owns 16 gate cols (8 r + 8 z) and 8 g cols, full (x||h) weight
// rows SMEM-resident as f32x2 pairs. 16 warps = (ks 0..7, bh 0..1):
//   phase A: ks<4 stream x chunk ks (32 k4) -> 12 accs (8 WA + 4 WB-x);
//            ks>=4 stream h chunk ks-4 (32 k4) -> 8 WA accs.
//   phase B: all warps stream r*h chunk ks (16 k4) -> 4 WB accs.
// x is read ONCE per wavefront (WB-x partials stashed in xred across the
// barrier). h per (b,j) is register-resident in its combine thread.
// ---------------------------------------------------------------------------

#define TSTEPS 512
#define BATCH  64
#define HC     512
#define NCTA   128
#define NTHR   512

#define FFMA2(d, a, b) \
    asm("fma.rn.f32x2 %0, %1, %2, %0;" : "+l"(d) : "l"(a), "l"(b))
#define PACK2(d, lo, hi) \
    asm("mov.b64 %0, {%1, %2};" : "=l"(d) : "r"(__float_as_uint(lo)), "r"(__float_as_uint(hi)))
#define UNPACK2(lo, hi, s) do { unsigned _ulo, _uhi; \
    asm("mov.b64 {%0, %1}, %2;" : "=r"(_ulo), "=r"(_uhi) : "l"(s)); \
    lo = __uint_as_float(_ulo); hi = __uint_as_float(_uhi); } while (0)

typedef unsigned long long ull;

// Packed streaming layouts: [k4][b][s] (float4 per (k4,b))
__device__ float g_xT [TSTEPS * BATCH * HC];
__device__ float g_h1T[TSTEPS * BATCH * HC];
__device__ float g_hT [2 * BATCH * HC];
__device__ float g_rhT[2 * BATCH * HC];
__device__ unsigned          g_arrive;
__device__ volatile unsigned g_gen;

__device__ __forceinline__ void grid_barrier(unsigned n) {
    __syncthreads();
    if (threadIdx.x == 0) {
        __threadfence();
        unsigned a = atomicAdd(&g_arrive, 1u);
        if (a == n * NCTA + (NCTA - 1)) {
            atomicExch((unsigned*)&g_gen, n + 1u);
        } else {
            while (g_gen < n + 1u) { }
        }
        __threadfence();
    }
    __syncthreads();
}

// Prep: transpose x into packed layout, broadcast h0, reset barrier.
__global__ __launch_bounds__(256) void prep_kernel(const float* __restrict__ x,
                                                   const float* __restrict__ hid)
{
    const size_t o = (size_t)blockIdx.x * 256 + threadIdx.x;
    const int s  = (int)(o & 3);
    const int b  = (int)((o >> 2) & 63);
    const int k4 = (int)((o >> 8) & 127);
    const size_t t = o >> 15;
    g_xT[o] = x[(t * 64 + b) * 512 + k4 * 4 + s];
    if (o < 2 * 32768) {
        const int l = (int)(o >> 15);
        g_hT[o] = hid[l * 512 + k4 * 4 + s];
    }
    if (o == 0) { g_arrive = 0u; *(unsigned*)&g_gen = 0u; }
}

__global__ __launch_bounds__(NTHR, 1) void gru_fused(
    const float* __restrict__ W1, const float* __restrict__ W2,
    const float* __restrict__ bias1, const float* __restrict__ bias2,
    const float* __restrict__ hid,
    float* __restrict__ out_seq, float* __restrict__ out_hs)
{
    extern __shared__ ull smem[];
    ull* WAp  = smem;               // [k<1024][jp<8]  : 8192 ull = 64 KB
    ull* WBp  = WAp + 8192;         // [k<1024][jp<4]  : 4096 ull = 32 KB
    ull* red  = WBp + 4096;         // [jp<8][512]     : 4096 ull = 32 KB
    ull* xred = red + 4096;         // [jp<4][512]     : 2048 ull = 16 KB
    float* zbuf = (float*)(xred + 2048);   // [64][8]   :  512 f  =  2 KB

    const int c = blockIdx.x, tid = threadIdx.x;
    const int layer = c >> 6, cl = c & 63;
    const int w = tid >> 5, lane = tid & 31;
    const int ks = w >> 1, bh = w & 1;
    const int b = bh * 32 + lane;

    const float* W1L = W1 + (size_t)layer * 1024 * 1024;
    const float* W2L = W2 + (size_t)layer * 512 * 1024;

    // Pack weights: WAp jp<4 = r col pairs, jp>=4 = z col pairs; WBp = g pairs.
    for (int i = tid; i < 8192; i += NTHR) {
        const int jp = i >> 10, k = i & 1023;
        const int jr = (jp < 4) ? (cl * 8 + 2 * jp) : (512 + cl * 8 + 2 * (jp - 4));
        ull u;
        PACK2(u, W1L[(size_t)jr * 1024 + k], W1L[(size_t)(jr + 1) * 1024 + k]);
        WAp[(size_t)k * 8 + jp] = u;
    }
    for (int i = tid; i < 4096; i += NTHR) {
        const int jp = i >> 10, k = i & 1023;
        const int jr = cl * 8 + 2 * jp;
        ull u;
        PACK2(u, W2L[(size_t)jr * 1024 + k], W2L[(size_t)(jr + 1) * 1024 + k]);
        WBp[(size_t)k * 4 + jp] = u;
    }

    // Combine-thread mapping: b2 = tid>>3 (batch), q = tid&7.
    // q<4: owns r-pair jp=q AND g-pair jp=q (h register-resident);
    // q>=4: owns z-pair jp=q (writes zbuf).
    const int b2 = tid >> 3, q = tid & 7;
    const int j0 = cl * 8 + 2 * (q & 3);
    const float bA0 = (q < 4) ? bias1[(size_t)layer * 1024 + j0]
                              : bias1[(size_t)layer * 1024 + 512 + j0];
    const float bA1 = (q < 4) ? bias1[(size_t)layer * 1024 + j0 + 1]
                              : bias1[(size_t)layer * 1024 + 512 + j0 + 1];
    const float bG0 = bias2[(size_t)layer * 512 + j0];
    const float bG1 = bias2[(size_t)layer * 512 + j0 + 1];
    float h0r = hid[layer * 512 + j0];
    float h1r = hid[layer * 512 + j0 + 1];

    float* hTl  = g_hT  + (size_t)layer * 32768;
    float* rhTl = g_rhT + (size_t)layer * 32768;
    const float4* hT4  = (const float4*)hTl;
    const float4* rhT4 = (const float4*)rhTl;
    const int bh2 = b2 >> 5, bl = b2 & 31;

    __syncthreads();

    for (int wf = 0; wf <= TSTEPS; wf++) {
        const bool active = layer ? (wf >= 1) : (wf < TSTEPS);
        const int t = layer ? (wf - 1) : wf;
        const float4* xsrc = (const float4*)((layer ? g_h1T : g_xT) + (size_t)t * 32768);

        if (active) {
            // ================= phase A =================
            if (ks < 4) {
                // x-warp: chunk ks (32 k4), 8 WA accs + 4 WB-x accs
                ull acc[12];
                #pragma unroll
                for (int p = 0; p < 12; p++) acc[p] = 0ull;
                const float4* sp = xsrc + (size_t)(ks * 32) * 64 + b;
                float4 buf[4];
                #pragma unroll
                for (int d = 0; d < 4; d++) buf[d] = __ldcg(sp + (size_t)d * 64);
                #pragma unroll 2
                for (int ib = 0; ib < 8; ib++) {
                    #pragma unroll
                    for (int u = 0; u < 4; u++) {
                        const int i = ib * 4 + u;
                        const float4 v = buf[u];
                        if (i + 4 < 32) buf[u] = __ldcg(sp + (size_t)(i + 4) * 64);
                        const float vs[4] = {v.x, v.y, v.z, v.w};
                        #pragma unroll
                        for (int s = 0; s < 4; s++) {
                            const int k = (ks * 32 + i) * 4 + s;
                            ull vd; PACK2(vd, vs[s], vs[s]);
                            const ulonglong2* wa = (const ulonglong2*)&WAp[(size_t)k * 8];
                            const ulonglong2* wb = (const ulonglong2*)&WBp[(size_t)k * 4];
                            const ulonglong2 a0 = wa[0], a1 = wa[1], a2 = wa[2], a3 = wa[3];
                            const ulonglong2 c0 = wb[0], c1 = wb[1];
                            FFMA2(acc[0], vd, a0.x); FFMA2(acc[1], vd, a0.y);
                            FFMA2(acc[2], vd, a1.x); FFMA2(acc[3], vd, a1.y);
                            FFMA2(acc[4], vd, a2.x); FFMA2(acc[5], vd, a2.y);
                            FFMA2(acc[6], vd, a3.x); FFMA2(acc[7], vd, a3.y);
                            FFMA2(acc[8], vd, c0.x); FFMA2(acc[9], vd, c0.y);
                            FFMA2(acc[10], vd, c1.x); FFMA2(acc[11], vd, c1.y);
                        }
                    }
                }
                #pragma unroll
                for (int jp = 0; jp < 8; jp++) red[jp * NTHR + tid] = acc[jp];
                #pragma unroll
                for (int jp = 0; jp < 4; jp++) xred[jp * NTHR + tid] = acc[8 + jp];
            } else {
                // h-warp: chunk ks-4 (32 k4) of h, 8 WA accs
                ull acc[8];
                #pragma unroll
                for (int p = 0; p < 8; p++) acc[p] = 0ull;
                const float4* sp = hT4 + (size_t)((ks - 4) * 32) * 64 + b;
                float4 buf[4];
                #pragma unroll
                for (int d = 0; d < 4; d++) buf[d] = __ldcg(sp + (size_t)d * 64);
                #pragma unroll 2
                for (int ib = 0; ib < 8; ib++) {
                    #pragma unroll
                    for (int u = 0; u < 4; u++) {
                        const int i = ib * 4 + u;
                        const float4 v = buf[u];
                        if (i + 4 < 32) buf[u] = __ldcg(sp + (size_t)(i + 4) * 64);
                        const float vs[4] = {v.x, v.y, v.z, v.w};
                        #pragma unroll
                        for (int s = 0; s < 4; s++) {
                            const int k = 512 + ((ks - 4) * 32 + i) * 4 + s;
                            ull vd; PACK2(vd, vs[s], vs[s]);
                            const ulonglong2* wa = (const ulonglong2*)&WAp[(size_t)k * 8];
                            const ulonglong2 a0 = wa[0], a1 = wa[1], a2 = wa[2], a3 = wa[3];
                            FFMA2(acc[0], vd, a0.x); FFMA2(acc[1], vd, a0.y);
                            FFMA2(acc[2], vd, a1.x); FFMA2(acc[3], vd, a1.y);
                            FFMA2(acc[4], vd, a2.x); FFMA2(acc[5], vd, a2.y);
                            FFMA2(acc[6], vd, a3.x); FFMA2(acc[7], vd, a3.y);
                        }
                    }
                }
                #pragma unroll
                for (int jp = 0; jp < 8; jp++) red[jp * NTHR + tid] = acc[jp];
            }
            __syncthreads();
            // combine A: all 512 threads; thread (b2,q) sums 8 warp partials
            {
                float s0 = 0.f, s1 = 0.f;
                #pragma unroll
                for (int kk = 0; kk < 8; kk++) {
                    const int slot = (kk * 2 + bh2) * 32 + bl;
                    float lo, hi;
                    UNPACK2(lo, hi, red[q * NTHR + slot]);
                    s0 += lo; s1 += hi;
                }
                const float sg0 = 1.f / (1.f + __expf(-(s0 + bA0)));
                const float sg1 = 1.f / (1.f + __expf(-(s1 + bA1)));
                if (q < 4) {       // r pair -> r*h (h register-resident)
                    float2 rh; rh.x = sg0 * h0r; rh.y = sg1 * h1r;
                    *(float2*)&rhTl[((j0 >> 2) * 64 + b2) * 4 + (j0 & 3)] = rh;
                } else {           // z pair
                    zbuf[b2 * 8 + 2 * (q & 3)]     = sg0;
                    zbuf[b2 * 8 + 2 * (q & 3) + 1] = sg1;
                }
            }
        }
        grid_barrier(2u * (unsigned)wf);

        if (active) {
            // ================= phase B: rh only =================
            {
                ull acc[4];
                #pragma unroll
                for (int p = 0; p < 4; p++) acc[p] = 0ull;
                const float4* sp = rhT4 + (size_t)(ks * 16) * 64 + b;
                float4 buf[4];
                #pragma unroll
                for (int d = 0; d < 4; d++) buf[d] = __ldcg(sp + (size_t)d * 64);
                #pragma unroll
                for (int ib = 0; ib < 4; ib++) {
                    #pragma unroll
                    for (int u = 0; u < 4; u++) {
                        const int i = ib * 4 + u;
                        const float4 v = buf[u];
                        if (i + 4 < 16) buf[u] = __ldcg(sp + (size_t)(i + 4) * 64);
                        const float vs[4] = {v.x, v.y, v.z, v.w};
                        #pragma unroll
                        for (int s = 0; s < 4; s++) {
                            const int k = 512 + (ks * 16 + i) * 4 + s;
                            ull vd; PACK2(vd, vs[s], vs[s]);
                            const ulonglong2* wb = (const ulonglong2*)&WBp[(size_t)k * 4];
                            const ulonglong2 c0 = wb[0], c1 = wb[1];
                            FFMA2(acc[0], vd, c0.x); FFMA2(acc[1], vd, c0.y);
                            FFMA2(acc[2], vd, c1.x); FFMA2(acc[3], vd, c1.y);
                        }
                    }
                }
                #pragma unroll
                for (int jp = 0; jp < 4; jp++) red[jp * NTHR + tid] = acc[jp];
            }
            __syncthreads();
            if (q < 4) {
                float s0 = 0.f, s1 = 0.f;
                #pragma unroll
                for (int kk = 0; kk < 8; kk++) {     // rh partials (8 k-chunks)
                    const int slot = (kk * 2 + bh2) * 32 + bl;
                    float lo, hi;
                    UNPACK2(lo, hi, red[q * NTHR + slot]);
                    s0 += lo; s1 += hi;
                }
                #pragma unroll
                for (int kk = 0; kk < 4; kk++) {     // x-part partials (phase A)
                    const int slot = (kk * 2 + bh2) * 32 + bl;
                    float lo, hi;
                    UNPACK2(lo, hi, xred[q * NTHR + slot]);
                    s0 += lo; s1 += hi;
                }
                const float g0 = tanhf(s0 + bG0);
                const float g1 = tanhf(s1 + bG1);
                const float z0 = zbuf[b2 * 8 + 2 * q];
                const float z1 = zbuf[b2 * 8 + 2 * q + 1];
                const float hn0 = z0 * h0r + (1.f - z0) * g0;
                const float hn1 = z1 * h1r + (1.f - z1) * g1;
                h0r = hn0; h1r = hn1;
                float2 hv; hv.x = hn0; hv.y = hn1;
                *(float2*)&hTl[((j0 >> 2) * 64 + b2) * 4 + (j0 & 3)] = hv;
                if (layer == 0)
                    *(float2*)&g_h1T[((size_t)t * 128 + (j0 >> 2)) * 256 + b2 * 4 + (j0 & 3)] = hv;
                else
                    *(float2*)&out_seq[((size_t)t * 64 + b2) * 512 + j0] = hv;
                if (t == TSTEPS - 1)
                    *(float2*)&out_hs[(size_t)layer * 32768 + b2 * 512 + j0] = hv;
            }
        }
        grid_barrier(2u * (unsigned)wf + 1u);
    }
}

// ---------------------------------------------------------------------------
// Inputs: x[512,64,512], hiddens[2,1,512], W1[2,1024,1024], b1[2,1024],
//         W2[2,512,1024], b2[2,512]
// Output: out_seq[512,64,512] ++ hs[2,64,512]
// ---------------------------------------------------------------------------
extern "C" void kernel_launch(void* const* d_in, const int* in_sizes, int n_in,
                              void* d_out, int out_size)
{
    const float* x   = (const float*)d_in[0];
    const float* hid = (const float*)d_in[1];
    const float* W1  = (const float*)d_in[2];
    const float* b1  = (const float*)d_in[3];
    const float* W2  = (const float*)d_in[4];
    const float* b2  = (const float*)d_in[5];

    float* out_seq = (float*)d_out;
    float* out_hs  = (float*)d_out + (size_t)TSTEPS * BATCH * HC;

    const int SMEM_BYTES = (8192 + 4096 + 4096 + 2048) * 8 + 2048;  // 149504
    cudaFuncSetAttribute(gru_fused, cudaFuncAttributeMaxDynamicSharedMemorySize,
                         SMEM_BYTES);

    prep_kernel<<<(TSTEPS * BATCH * HC) / 256, 256>>>(x, hid);
    gru_fused<<<NCTA, NTHR, SMEM_BYTES>>>(W1, W2, b1, b2, hid, out_seq, out_hs);
}